// round 11
// baseline (speedup 1.0000x reference)
#include <cuda_runtime.h>
#include <cuda_bf16.h>
#include <stdint.h>

#define N_NODES 131072
#define N_EDGES 256
#define IN_C    128
#define OUT_C   256
#define M_TILE  64
#define N_TILES (N_NODES / M_TILE)    // 2048
#define TILE_BYTES 32768              // AH 16K + A8 8K + AL8 8K
#define SAT_NODES 8192

// ---------------- device scratch (no allocations allowed) ----------------
__device__ __align__(16) uint32_t g_nodeMask[N_NODES * 8];   // 4 MB (fallback only)
__device__ uint32_t g_edgeMask[N_EDGES * 8];                 // 8 KB
__device__ float    g_scale[N_NODES];
__device__ int      g_sat;
__device__ __align__(128) char g_Ablob[(size_t)N_TILES * TILE_BYTES];  // 64 MB

// ---------------- shared helpers ----------------
__device__ __forceinline__ uint32_t sw_off(int row, int k) {     // bf16, 256B rows
    return (uint32_t)(row * 256 + ((((k >> 3) ^ (row & 7)) << 4) | ((k & 7) * 2)));
}
__device__ __forceinline__ uint32_t sw8_off(int row, int k) {    // fp8, 128B rows
    return (uint32_t)(row * 128 + ((((k >> 4) ^ (row & 7)) << 4) | (k & 15)));
}

__device__ __forceinline__ uint32_t smem_u32(const void* p) {
    uint32_t a;
    asm("{ .reg .u64 t; cvta.to.shared.u64 t, %1; cvt.u32.u64 %0, t; }"
        : "=r"(a) : "l"(p));
    return a;
}

__device__ __forceinline__ void ldsm_x4(uint32_t* r, uint32_t addr) {
    asm volatile("ldmatrix.sync.aligned.m8n8.x4.shared.b16 {%0,%1,%2,%3}, [%4];"
                 : "=r"(r[0]), "=r"(r[1]), "=r"(r[2]), "=r"(r[3]) : "r"(addr));
}

__device__ __forceinline__ void mma16816(float* c, const uint32_t* a, const uint32_t* b) {
    asm volatile(
        "mma.sync.aligned.m16n8k16.row.col.f32.bf16.bf16.f32 "
        "{%0,%1,%2,%3}, {%4,%5,%6,%7}, {%8,%9}, {%0,%1,%2,%3};"
        : "+f"(c[0]), "+f"(c[1]), "+f"(c[2]), "+f"(c[3])
        : "r"(a[0]), "r"(a[1]), "r"(a[2]), "r"(a[3]), "r"(b[0]), "r"(b[1]));
}

__device__ __forceinline__ void mma_fp8(float* c, const uint32_t* a, const uint32_t* b) {
    asm volatile(
        "mma.sync.aligned.m16n8k32.row.col.f32.e4m3.e4m3.f32 "
        "{%0,%1,%2,%3}, {%4,%5,%6,%7}, {%8,%9}, {%0,%1,%2,%3};"
        : "+f"(c[0]), "+f"(c[1]), "+f"(c[2]), "+f"(c[3])
        : "r"(a[0]), "r"(a[1]), "r"(a[2]), "r"(a[3]), "r"(b[0]), "r"(b[1]));
}

__device__ __forceinline__ uint32_t pack4_e4m3(float f0, float f1, float f2, float f3) {
    uint16_t lo, hi;
    asm("cvt.rn.satfinite.e4m3x2.f32 %0, %1, %2;" : "=h"(lo) : "f"(f1), "f"(f0));
    asm("cvt.rn.satfinite.e4m3x2.f32 %0, %1, %2;" : "=h"(hi) : "f"(f3), "f"(f2));
    return (uint32_t)lo | ((uint32_t)hi << 16);
}

// 8 fp32 (row, k0..k0+7) -> AH(bf16) + A8(e4m3) + AL8(e4m3 resid*256); base = smem OR gmem
__device__ __forceinline__ void convert8(const float* v, char* base, int row, int k0,
                                         uint32_t offH, uint32_t off8, uint32_t offL8) {
    uint32_t hi[4];
    float r[8];
    #pragma unroll
    for (int i = 0; i < 4; i++) {
        __nv_bfloat16 h0 = __float2bfloat16(v[2 * i + 0]);
        __nv_bfloat16 h1 = __float2bfloat16(v[2 * i + 1]);
        r[2 * i + 0] = (v[2 * i + 0] - __bfloat162float(h0)) * 256.0f;
        r[2 * i + 1] = (v[2 * i + 1] - __bfloat162float(h1)) * 256.0f;
        __nv_bfloat162 hp = __halves2bfloat162(h0, h1);
        hi[i] = *reinterpret_cast<uint32_t*>(&hp);
    }
    *reinterpret_cast<uint4*>(base + offH + sw_off(row, k0)) =
        make_uint4(hi[0], hi[1], hi[2], hi[3]);
    const uint32_t o8 = sw8_off(row, k0);
    *reinterpret_cast<uint2*>(base + off8 + o8) =
        make_uint2(pack4_e4m3(v[0], v[1], v[2], v[3]),
                   pack4_e4m3(v[4], v[5], v[6], v[7]));
    *reinterpret_cast<uint2*>(base + offL8 + o8) =
        make_uint2(pack4_e4m3(r[0], r[1], r[2], r[3]),
                   pack4_e4m3(r[4], r[5], r[6], r[7]));
}

// ---------------- K0: zero edge-mask table + flag ----------------
__global__ void k_zero() {
    int i = blockIdx.x * blockDim.x + threadIdx.x;
    if (i < N_EDGES * 8) g_edgeMask[i] = 0u;
    if (i == 0) g_sat = 0;
}

// ---------------- K1: pack sample nodes -> edge masks + per-node deg ----------------
__global__ void __launch_bounds__(512) k_pack1(const float* __restrict__ H) {
    __shared__ uint32_t sEdge[N_EDGES * 8];
    const int tid  = threadIdx.x;
    const int lane = tid & 31;
    const int w    = tid & 7;

    for (int i = tid; i < N_EDGES * 8; i += 512) sEdge[i] = 0u;
    __syncthreads();

    const int node = blockIdx.x * 64 + (tid >> 3);   // 128 blocks x 64 nodes
    {
        const float4* hp = reinterpret_cast<const float4*>(
            H + (size_t)node * N_EDGES + w * 32);
        uint32_t word = 0;
        #pragma unroll
        for (int j = 0; j < 8; j++) {
            float4 f = hp[j];
            word |= (f.x >= 0.5f ? 1u : 0u) << (j * 4 + 0);
            word |= (f.y >= 0.5f ? 1u : 0u) << (j * 4 + 1);
            word |= (f.z >= 0.5f ? 1u : 0u) << (j * 4 + 2);
            word |= (f.w >= 0.5f ? 1u : 0u) << (j * 4 + 3);
        }
        g_nodeMask[node * 8 + w] = word;
        int d = __popc(word);
        d += __shfl_xor_sync(0xffffffffu, d, 1);
        d += __shfl_xor_sync(0xffffffffu, d, 2);
        d += __shfl_xor_sync(0xffffffffu, d, 4);
        if (w == 0) g_scale[node] = (float)d;     // raw deg; k_sat converts

        uint32_t wd[8];
        #pragma unroll
        for (int j = 0; j < 8; j++)
            wd[j] = __shfl_sync(0xffffffffu, word, (lane & ~7) | j);
        uint32_t m = word;
        while (m) {
            int b = __ffs(m) - 1;
            m &= m - 1;
            int e = w * 32 + b;
            #pragma unroll
            for (int j = 0; j < 8; j++) {
                uint32_t cur = sEdge[e * 8 + j];
                if ((cur & wd[j]) != wd[j]) atomicOr(&sEdge[e * 8 + j], wd[j]);
            }
        }
    }
    __syncthreads();
    for (int i = tid; i < N_EDGES * 8; i += 512) {
        uint32_t v = sEdge[i];
        if (v) atomicOr(&g_edgeMask[i], v);
    }
}

// ---------------- K2: saturation check + scale for sample nodes ----------------
__global__ void __launch_bounds__(256) k_sat() {
    __shared__ int nf;
    const int tid = threadIdx.x;
    if (tid == 0) nf = 0;
    __syncthreads();
    int bad = 0;
    for (int i = tid; i < N_EDGES * 8; i += 256)
        bad += (g_edgeMask[i] != 0xffffffffu);
    atomicAdd(&nf, bad);
    __syncthreads();
    const bool sat = (nf == 0);
    if (blockIdx.x == 0 && tid == 0) g_sat = sat ? 1 : 0;
    if (sat) {
        const int node = blockIdx.x * 256 + tid;     // 32 x 256 = 8192
        if (node < SAT_NODES) {
            float d = g_scale[node];
            g_scale[node] = (d > 0.0f) ? (1.0f + rsqrtf(d + 256.0f)) : 1.0f;
        }
    }
}

// ---------------- K3: stream remaining nodes (coalesced saturated path) ----------------
__global__ void __launch_bounds__(512) k_pack2(const float* __restrict__ H) {
    __shared__ uint32_t sEdge[N_EDGES * 8];
    const int tid  = threadIdx.x;
    const int lane = tid & 31;
    const bool sat = (g_sat != 0);

    if (sat) {
        const int wId  = tid >> 5;          // 16 warps
        const int l16  = lane & 15;
        const int half = lane >> 4;
        for (int base = SAT_NODES + blockIdx.x * 32; base < N_NODES;
             base += gridDim.x * 32) {
            const int node = base + wId * 2 + half;
            int cnt = 0;
            if (node < N_NODES) {
                const float4* hp = reinterpret_cast<const float4*>(
                    H + (size_t)node * N_EDGES) + l16;
                const float4 v0 = hp[0];
                const float4 v1 = hp[16];
                const float4 v2 = hp[32];
                const float4 v3 = hp[48];
                cnt  = (v0.x >= 0.5f) + (v0.y >= 0.5f) + (v0.z >= 0.5f) + (v0.w >= 0.5f);
                cnt += (v1.x >= 0.5f) + (v1.y >= 0.5f) + (v1.z >= 0.5f) + (v1.w >= 0.5f);
                cnt += (v2.x >= 0.5f) + (v2.y >= 0.5f) + (v2.z >= 0.5f) + (v2.w >= 0.5f);
                cnt += (v3.x >= 0.5f) + (v3.y >= 0.5f) + (v3.z >= 0.5f) + (v3.w >= 0.5f);
            }
            cnt += __shfl_xor_sync(0xffffffffu, cnt, 1);
            cnt += __shfl_xor_sync(0xffffffffu, cnt, 2);
            cnt += __shfl_xor_sync(0xffffffffu, cnt, 4);
            cnt += __shfl_xor_sync(0xffffffffu, cnt, 8);
            if (l16 == 0 && node < N_NODES)
                g_scale[node] = (cnt > 0) ? (1.0f + rsqrtf((float)(cnt + 256))) : 1.0f;
        }
        return;
    }

    // ---- exact fallback (rare) ----
    const int w = tid & 7;
    for (int i = tid; i < N_EDGES * 8; i += 512) sEdge[i] = 0u;
    __syncthreads();

    for (int base = SAT_NODES + blockIdx.x * 64; base < N_NODES; base += gridDim.x * 64) {
        const int node = base + (tid >> 3);
        const float4* hp = reinterpret_cast<const float4*>(
            H + (size_t)node * N_EDGES + w * 32);
        uint32_t word = 0;
        #pragma unroll
        for (int j = 0; j < 8; j++) {
            float4 f = hp[j];
            word |= (f.x >= 0.5f ? 1u : 0u) << (j * 4 + 0);
            word |= (f.y >= 0.5f ? 1u : 0u) << (j * 4 + 1);
            word |= (f.z >= 0.5f ? 1u : 0u) << (j * 4 + 2);
            word |= (f.w >= 0.5f ? 1u : 0u) << (j * 4 + 3);
        }
        g_nodeMask[node * 8 + w] = word;
        uint32_t wd[8];
        #pragma unroll
        for (int j = 0; j < 8; j++)
            wd[j] = __shfl_sync(0xffffffffu, word, (lane & ~7) | j);
        uint32_t m = word;
        while (m) {
            int b = __ffs(m) - 1;
            m &= m - 1;
            int e = w * 32 + b;
            #pragma unroll
            for (int j = 0; j < 8; j++) {
                uint32_t cur = sEdge[e * 8 + j];
                if ((cur & wd[j]) != wd[j]) atomicOr(&sEdge[e * 8 + j], wd[j]);
            }
        }
    }
    __syncthreads();
    for (int i = tid; i < N_EDGES * 8; i += 512) {
        uint32_t v = sEdge[i];
        if (v) atomicOr(&g_edgeMask[i], v);
    }
}

// ---------------- K4 (fallback, rare): exact scale for ALL nodes ----------------
__global__ void __launch_bounds__(256) k_fb_scale() {
    if (g_sat) return;
    __shared__ uint32_t tbl[N_EDGES * 8];
    const int tid = threadIdx.x;
    for (int i = tid; i < N_EDGES * 8; i += 256) tbl[i] = g_edgeMask[i];
    __syncthreads();

    for (int node = blockIdx.x * 256 + tid; node < N_NODES; node += gridDim.x * 256) {
        const uint4 a = reinterpret_cast<const uint4*>(g_nodeMask)[node * 2 + 0];
        const uint4 b = reinterpret_cast<const uint4*>(g_nodeMask)[node * 2 + 1];
        uint32_t wd[8] = {a.x, a.y, a.z, a.w, b.x, b.y, b.z, b.w};
        int deg = 0;
        #pragma unroll
        for (int j = 0; j < 8; j++) deg += __popc(wd[j]);
        uint32_t acc[8] = {0, 0, 0, 0, 0, 0, 0, 0};
        if (deg) {
            bool fl = false;
            for (int w0 = 0; w0 < 8 && !fl; w0++) {
                uint32_t m = wd[w0];
                while (m) {
                    int bi = __ffs(m) - 1;
                    m &= m - 1;
                    int e = w0 * 32 + bi;
                    uint32_t allones = 0xffffffffu;
                    #pragma unroll
                    for (int j = 0; j < 8; j++) {
                        acc[j] |= tbl[e * 8 + j];
                        allones &= acc[j];
                    }
                    if (allones == 0xffffffffu) { fl = true; break; }
                }
            }
        }
        int dv2 = 0;
        #pragma unroll
        for (int j = 0; j < 8; j++) dv2 += __popc(acc[j]);
        const int dv = deg + dv2;
        float s = 1.0f;
        if (dv > 0) s += rsqrtf((float)dv);
        g_scale[node] = s;
    }
}

// ---------------- K5: convert U -> per-tile smem-image blob (swizzled) ----------------
__global__ void __launch_bounds__(256) k_conv(const float* __restrict__ U) {
    const int tile = blockIdx.x;                 // 2048 blocks
    char* gbase = g_Ablob + (size_t)tile * TILE_BYTES;
    const int R0 = tile * M_TILE;
    #pragma unroll
    for (int it = 0; it < 4; it++) {
        const int c  = it * 256 + threadIdx.x;   // 0..1023
        const int m  = c >> 4;
        const int k0 = (c & 15) * 8;
        const float4* up = reinterpret_cast<const float4*>(
            U + (size_t)(R0 + m) * IN_C + k0);
        const float4 f0 = up[0];
        const float4 f1 = up[1];
        float v[8] = {f0.x, f0.y, f0.z, f0.w, f1.x, f1.y, f1.z, f1.w};
        convert8(v, gbase, m, k0, 0u, 16384u, 24576u);
    }
}

// ---------------- K6: GEMM out = scale * (U @ W) + bias ----------------
// 512 threads, M_TILE=64 tiles streamed via cp.async from the pre-converted
// blob, double-buffered. Warp grid 2M x 8N (32x32 warp tiles, full 256 cols).
#define SM_BIAS  0                       // 256 floats = 1 KB
#define SM_SCALE 1024                    // 2 x 64 floats
#define SM_A     2048                    // 2 x 32 KB A stages
#define SM_BH    (SM_A + 2 * TILE_BYTES) // 67584: 256 x 256B bf16  64 KB
#define SM_B8    (SM_BH + 65536)         // 256 x 128B fp8          32 KB
#define SM_BL8   (SM_B8 + 32768)         //                         32 KB
#define SM_TOTAL (SM_BL8 + 32768)        // 198656 bytes

#define CP_ASYNC16(sm, gm) \
    asm volatile("cp.async.cg.shared.global [%0], [%1], 16;" \
                 :: "r"(sm), "l"(gm) : "memory")

__global__ void __launch_bounds__(512, 1)
k_gemm(const float* __restrict__ W, const float* __restrict__ bias,
       float* __restrict__ out)
{
    extern __shared__ char smem[];
    const uint32_t sb = smem_u32(smem);
    const int tid  = threadIdx.x;
    const int wid  = tid >> 5;          // 0..15
    const int lane = tid & 31;
    const int wm   = wid >> 3;          // 0..1 (32 rows each)
    const int wn   = wid & 7;           // 0..7 (32 cols each)

    float* sbias  = reinterpret_cast<float*>(smem + SM_BIAS);
    float* sscale = reinterpret_cast<float*>(smem + SM_SCALE);
    if (tid < OUT_C) sbias[tid] = bias[tid];

    // ---- convert W once ----
    #pragma unroll 1
    for (int it = 0; it < 8; it++) {
        const int idx = it * 512 + tid;
        const int n   = idx & 255;
        const int k0  = (idx >> 8) * 8;
        float v[8];
        #pragma unroll
        for (int i = 0; i < 8; i++) v[i] = W[(size_t)(k0 + i) * OUT_C + n];
        convert8(v, smem, n, k0, SM_BH, SM_B8, SM_BL8);
    }

    const uint32_t xr = lane & 7;
    const uint32_t aRowB = (uint32_t)(((wm << 5) + (lane & 15)) * 256);
    const uint32_t aRow8 = (uint32_t)(((wm << 5) + (lane & 15)) * 128);
    const int nInPair = (lane & 7) + ((lane >> 4) << 3);
    const uint32_t bKcOff = (lane >> 3) & 1;
    const uint32_t aKcOff = lane >> 4;
    const int ncolw = wn * 32;

    // ---- prologue: stage tile t0 into buffer 0 ----
    const int t0 = blockIdx.x;
    {
        const char* gsrc = g_Ablob + (size_t)t0 * TILE_BYTES;
        #pragma unroll
        for (int i = 0; i < 4; i++) {
            const int c = i * 512 + tid;
            CP_ASYNC16(sb + SM_A + (uint32_t)(c * 16), gsrc + c * 16);
        }
        asm volatile("cp.async.commit_group;" ::: "memory");
        if (tid < M_TILE) sscale[tid] = g_scale[t0 * M_TILE + tid];
        asm volatile("cp.async.wait_group 0;" ::: "memory");
    }
    __syncthreads();

    int p = 0;
    for (int tile = t0; tile < N_TILES; tile += 148, p ^= 1) {
        const int R0  = tile * M_TILE;
        const int nxt = tile + 148;
        const bool hasNext = (nxt < N_TILES);
        const uint32_t curA = sb + SM_A + (uint32_t)(p * TILE_BYTES);

        // issue next tile's cp.async into the other buffer (lands under MMAs)
        if (hasNext) {
            const char* gsrc = g_Ablob + (size_t)nxt * TILE_BYTES;
            const uint32_t sdst = sb + SM_A + (uint32_t)((p ^ 1) * TILE_BYTES);
            #pragma unroll
            for (int i = 0; i < 4; i++) {
                const int c = i * 512 + tid;
                CP_ASYNC16(sdst + (uint32_t)(c * 16), gsrc + c * 16);
            }
            asm volatile("cp.async.commit_group;" ::: "memory");
        }
        float gsc = 0.0f;
        if (hasNext && tid < M_TILE) gsc = g_scale[nxt * M_TILE + tid];

        float acc[32];
        #pragma unroll
        for (int i = 0; i < 32; i++) acc[i] = 0.0f;

        // ---- fp8 correction passes ----
        #pragma unroll
        for (int kc = 0; kc < 4; kc++) {
            const uint32_t kxA = ((((uint32_t)kc << 1) + aKcOff) ^ xr) << 4;
            uint32_t bofs[2];
            #pragma unroll
            for (int np = 0; np < 2; np++) {
                const int n_l = ncolw + np * 16 + nInPair;
                bofs[np] = (uint32_t)(n_l * 128) +
                           (((((uint32_t)kc << 1) + bKcOff) ^ (uint32_t)(n_l & 7)) << 4);
            }
            {   // C1: e4m3(A) x e4m3(Bl*256)
                uint32_t a[2][4];
                #pragma unroll
                for (int mt = 0; mt < 2; mt++)
                    ldsm_x4(a[mt], curA + 16384u + aRow8 + (uint32_t)(mt * 2048) + kxA);
                uint32_t b[2][4];
                ldsm_x4(b[0], sb + SM_BL8 + bofs[0]);
                ldsm_x4(b[1], sb + SM_BL8 + bofs[1]);
                #pragma unroll
                for (int mt = 0; mt < 2; mt++)
                    #pragma unroll
                    for (int np = 0; np < 2; np++) {
                        mma_fp8(&acc[(mt * 4 + np * 2 + 0) * 4], a[mt], &b[np][0]);
                        mma_fp8(&acc[(mt * 4 + np * 2 + 1) * 4], a[mt], &b[np][2]);
                    }
            }
            {   // C2: e4m3(Al*256) x e4m3(B)
                uint32_t a[2][4];
                #pragma unroll
                for (int mt = 0; mt < 2; mt++)
                    ldsm_x4(a[mt], curA + 24576u + aRow8 + (uint32_t)(mt * 2048) + kxA);
                uint32_t b[2][4];
                ldsm_x4(b[0], sb + SM_B8 + bofs[0]);
                ldsm_x4(b[1], sb + SM_B8 + bofs[1]);
                #pragma unroll
                for (int mt = 0; mt < 2; mt++)
                    #pragma unroll
                    for (int np = 0; np < 2; np++) {
                        mma_fp8(&acc[(mt * 4 + np * 2 + 0) * 4], a[mt], &b[np][0]);
                        mma_fp8(&acc[(mt * 4 + np * 2 + 1) * 4], a[mt], &b[np][2]);
                    }
            }
        }
        #pragma unroll
        for (int i = 0; i < 32; i++) acc[i] *= (1.0f / 256.0f);

        // ---- main pass: Ah x Bh (bf16) ----
        #pragma unroll
        for (int ks = 0; ks < 8; ks++) {
            uint32_t a[2][4];
            #pragma unroll
            for (int mt = 0; mt < 2; mt++) {
                const uint32_t kx = (((uint32_t)(2 * ks) + aKcOff) ^ xr) << 4;
                ldsm_x4(a[mt], curA + aRowB + (uint32_t)(mt * 4096) + kx);
            }
            uint32_t b[2][4];
            #pragma unroll
            for (int np = 0; np < 2; np++) {
                const int n_l = ncolw + np * 16 + nInPair;
                const uint32_t kx = (((uint32_t)(2 * ks) + bKcOff) ^ (uint32_t)(n_l & 7)) << 4;
                ldsm_x4(b[np], sb + SM_BH + (uint32_t)(n_l * 256) + kx);
            }
            #pragma unroll
            for (int mt = 0; mt < 2; mt++)
                #pragma unroll
                for (int np = 0; np < 2; np++) {
                    mma16816(&acc[(mt * 4 + np * 2 + 0) * 4], a[mt], &b[np][0]);
                    mma16816(&acc[(mt * 4 + np * 2 + 1) * 4], a[mt], &b[np][2]);
                }
        }

        // ---- epilogue: out = scale[row] * acc + bias[col] ----
        #pragma unroll
        for (int mt = 0; mt < 2; mt++) {
            const int r0 = (wm << 5) + mt * 16 + (lane >> 2);
            const float s0 = sscale[p * M_TILE + r0];
            const float s1 = sscale[p * M_TILE + r0 + 8];
            #pragma unroll
            for (int nt = 0; nt < 4; nt++) {
                const int col = ncolw + nt * 8 + (lane & 3) * 2;
                const float bx = sbias[col];
                const float by = sbias[col + 1];
                const float* c = &acc[(mt * 4 + nt) * 4];
                float2 o0 = make_float2(c[0] * s0 + bx, c[1] * s0 + by);
                float2 o1 = make_float2(c[2] * s1 + bx, c[3] * s1 + by);
                *reinterpret_cast<float2*>(out + (size_t)(R0 + r0) * OUT_C + col)     = o0;
                *reinterpret_cast<float2*>(out + (size_t)(R0 + r0 + 8) * OUT_C + col) = o1;
            }
        }

        // publish next tile's scales, then wait for its A stage
        if (hasNext && tid < M_TILE) sscale[(p ^ 1) * M_TILE + tid] = gsc;
        asm volatile("cp.async.wait_group 0;" ::: "memory");
        __syncthreads();
    }
}

// ---------------- launch ----------------
extern "C" void kernel_launch(void* const* d_in, const int* in_sizes, int n_in,
                              void* d_out, int out_size) {
    (void)in_sizes; (void)n_in; (void)out_size;
    const float* H    = (const float*)d_in[0];
    const float* U    = (const float*)d_in[1];
    const float* W    = (const float*)d_in[2];
    const float* bias = (const float*)d_in[3];
    float* out = (float*)d_out;

    k_zero<<<8, 256>>>();
    k_pack1<<<SAT_NODES / 64, 512>>>(H);
    k_sat<<<32, 256>>>();
    k_pack2<<<592, 512>>>(H);
    k_fb_scale<<<512, 256>>>();               // early-exits when saturated
    k_conv<<<N_TILES, 256>>>(U);

    cudaFuncSetAttribute(k_gemm, cudaFuncAttributeMaxDynamicSharedMemorySize, SM_TOTAL);
    k_gemm<<<148, 512, SM_TOTAL>>>(W, bias, out);
}